// round 3
// baseline (speedup 1.0000x reference)
#include <cuda_runtime.h>
#include <cuda_bf16.h>
#include <math.h>
#include <cstdint>

#define NN   40000
#define EE   640000
#define HIDN 128

// ------------------------- scratch (no allocations allowed) -----------------
__device__ __align__(16) float g_h[NN * HIDN];     // node state
__device__ __align__(16) float g_feat[NN * HIDN];  // GAT fc output
__device__ __align__(16) float g_gru[NN * 384];    // GRU gate pre-activations
__device__ __align__(16) float g_acc[NN * HIDN];   // unnormalized message sums
__device__ __align__(16) float g_el[NN * 4];
__device__ __align__(16) float g_er[NN * 4];
__device__ __align__(16) float g_emax[NN * 4];
__device__ __align__(16) float g_den[NN * 4];
__device__ __align__(16) float g_e[EE * 4];        // per-edge attention logits

// ------------------------- helpers ------------------------------------------
__device__ __forceinline__ uint32_t smem_u32(const void* p) {
    uint32_t a;
    asm("{ .reg .u64 t; cvta.to.shared.u64 t, %1; cvt.u32.u64 %0, t; }" : "=r"(a) : "l"(p));
    return a;
}

__device__ __forceinline__ float lrelu(float x) { return x > 0.f ? x : 0.2f * x; }

__device__ __forceinline__ void atomicMaxF(float* addr, float v) {
    if (v == 0.f) v = 0.f;  // canonicalize -0 -> +0
    if (v >= 0.f)
        atomicMax((int*)addr, __float_as_int(v));
    else
        atomicMin((unsigned int*)addr, (unsigned int)__float_as_int(v));
}

__device__ __forceinline__ void redAdd4(float* p, float a, float b, float c, float d) {
    asm volatile("red.global.add.v4.f32 [%0], {%1, %2, %3, %4};"
                 :: "l"(p), "f"(a), "f"(b), "f"(c), "f"(d) : "memory");
}

// ------------------------- mma.sync / ldmatrix primitives --------------------
__device__ __forceinline__ void ldm_x4(uint32_t& r0, uint32_t& r1, uint32_t& r2,
                                       uint32_t& r3, uint32_t addr) {
    asm volatile("ldmatrix.sync.aligned.m8n8.x4.shared.b16 {%0,%1,%2,%3}, [%4];"
                 : "=r"(r0), "=r"(r1), "=r"(r2), "=r"(r3) : "r"(addr));
}

__device__ __forceinline__ void mma_bf16(float* c, uint32_t a0, uint32_t a1,
                                         uint32_t a2, uint32_t a3,
                                         uint32_t b0, uint32_t b1) {
    asm volatile(
        "mma.sync.aligned.m16n8k16.row.col.f32.bf16.bf16.f32 "
        "{%0,%1,%2,%3}, {%4,%5,%6,%7}, {%8,%9}, {%0,%1,%2,%3};"
        : "+f"(c[0]), "+f"(c[1]), "+f"(c[2]), "+f"(c[3])
        : "r"(a0), "r"(a1), "r"(a2), "r"(a3), "r"(b0), "r"(b1));
}

// ------------------------- split-bf16 pack ----------------------------------
struct HL { uint32_t hi, lo; };
__device__ __forceinline__ HL split_pack(float a, float b) {
    __nv_bfloat16 ah = __float2bfloat16(a);
    __nv_bfloat16 bh = __float2bfloat16(b);
    __nv_bfloat16 al = __float2bfloat16(a - __bfloat162float(ah));
    __nv_bfloat16 bl = __float2bfloat16(b - __bfloat162float(bh));
    HL r;
    r.hi = ((uint32_t)__bfloat16_as_ushort(bh) << 16) | (uint32_t)__bfloat16_as_ushort(ah);
    r.lo = ((uint32_t)__bfloat16_as_ushort(bl) << 16) | (uint32_t)__bfloat16_as_ushort(al);
    return r;
}

// ------------------------- HMMA GEMM (K = 128 fixed) -------------------------
// C[m, n0+j] (stride Ntot) = sum_k A[m,k] * W(k, n0+j) (+ bias)
// TRANSB=false: W = B[k * Ntot + n]  (B row-major [128, Ntot])
// TRANSB=true:  W = B[n * 128  + k]  (C = A @ B^T)
// Split-bf16: C = Ahi*Bhi + Ahi*Blo + Alo*Bhi  (fp32 accumulate in HMMA)
// smem: A/B tiles stored with 136-bf16 padded rows (272B stride, conflict-free
// ldmatrix). B stored [n][k] so plain ldmatrix gives the .col B fragment.
#define PAD 136
#define TILE_B (128 * PAD * 2)   // 34816 bytes per tile

template <bool TRANSB>
__global__ __launch_bounds__(256, 1)
void gemm_tc(const float* __restrict__ A, const float* __restrict__ B,
             const float* __restrict__ bias, float* __restrict__ C,
             int M, int Ntot)
{
    extern __shared__ __align__(16) char smem[];
    char* sAhi = smem;
    char* sAlo = smem + TILE_B;
    char* sBhi = smem + 2 * TILE_B;
    char* sBlo = smem + 3 * TILE_B;

    int tid = threadIdx.x, wid = tid >> 5, lane = tid & 31;
    int m0 = blockIdx.x * 128, n0 = blockIdx.y * 128;
    int warp_m = wid >> 1, warp_n = wid & 1;   // 4 x 2 warp grid, 32x64 per warp

    // ---- stage A (rows = m), split hi/lo ----
    {
        int r = tid >> 1, half = tid & 1;     // 2 threads per row, 64 cols each
        bool valid = (m0 + r) < M;
        const float4* rp = (const float4*)(A + (size_t)(m0 + r) * 128 + half * 64);
        char* dh = sAhi + (size_t)r * (PAD * 2) + half * 128;
        char* dl = sAlo + (size_t)r * (PAD * 2) + half * 128;
#pragma unroll
        for (int j = 0; j < 8; j++) {         // 8 floats per iter
            float4 v0 = make_float4(0.f, 0.f, 0.f, 0.f), v1 = v0;
            if (valid) { v0 = rp[j * 2]; v1 = rp[j * 2 + 1]; }
            HL p0 = split_pack(v0.x, v0.y), p1 = split_pack(v0.z, v0.w);
            HL p2 = split_pack(v1.x, v1.y), p3 = split_pack(v1.z, v1.w);
            *(uint4*)(dh + j * 16) = make_uint4(p0.hi, p1.hi, p2.hi, p3.hi);
            *(uint4*)(dl + j * 16) = make_uint4(p0.lo, p1.lo, p2.lo, p3.lo);
        }
    }
    // ---- stage B as [n][k], split hi/lo ----
    {
        int n = tid >> 1, half = tid & 1;
        char* dh = sBhi + (size_t)n * (PAD * 2) + half * 128;
        char* dl = sBlo + (size_t)n * (PAD * 2) + half * 128;
        if (TRANSB) {
            const float4* rp = (const float4*)(B + (size_t)(n0 + n) * 128 + half * 64);
#pragma unroll
            for (int j = 0; j < 8; j++) {
                float4 v0 = rp[j * 2], v1 = rp[j * 2 + 1];
                HL p0 = split_pack(v0.x, v0.y), p1 = split_pack(v0.z, v0.w);
                HL p2 = split_pack(v1.x, v1.y), p3 = split_pack(v1.z, v1.w);
                *(uint4*)(dh + j * 16) = make_uint4(p0.hi, p1.hi, p2.hi, p3.hi);
                *(uint4*)(dl + j * 16) = make_uint4(p0.lo, p1.lo, p2.lo, p3.lo);
            }
        } else {
            int kb = half * 64;
#pragma unroll 2
            for (int j = 0; j < 8; j++) {
                float v[8];
#pragma unroll
                for (int q = 0; q < 8; q++)
                    v[q] = B[(size_t)(kb + j * 8 + q) * Ntot + n0 + n];
                HL p0 = split_pack(v[0], v[1]), p1 = split_pack(v[2], v[3]);
                HL p2 = split_pack(v[4], v[5]), p3 = split_pack(v[6], v[7]);
                *(uint4*)(dh + j * 16) = make_uint4(p0.hi, p1.hi, p2.hi, p3.hi);
                *(uint4*)(dl + j * 16) = make_uint4(p0.lo, p1.lo, p2.lo, p3.lo);
            }
        }
    }
    __syncthreads();

    // ---- mainloop ----
    float c[2][8][4];
#pragma unroll
    for (int mi = 0; mi < 2; mi++)
#pragma unroll
        for (int f = 0; f < 8; f++)
#pragma unroll
            for (int q = 0; q < 4; q++) c[mi][f][q] = 0.f;

    uint32_t uAhi = smem_u32(sAhi), uAlo = smem_u32(sAlo);
    uint32_t uBhi = smem_u32(sBhi), uBlo = smem_u32(sBlo);

    // ldmatrix lane offsets (bytes)
    uint32_t aOff = (uint32_t)(warp_m * 32 + (lane & 15)) * (PAD * 2) + (lane >> 4) * 16;
    uint32_t bOff = (uint32_t)(warp_n * 64 + ((lane >> 4) & 1) * 8 + (lane & 7)) * (PAD * 2)
                  + ((lane >> 3) & 1) * 16;

#pragma unroll 2
    for (int k0 = 0; k0 < 128; k0 += 16) {
        uint32_t kB = (uint32_t)k0 * 2;
        uint32_t ahi[2][4], alo[2][4], bhi[8][2], blo[8][2];
#pragma unroll
        for (int mi = 0; mi < 2; mi++) {
            uint32_t ad = aOff + mi * 16 * (PAD * 2) + kB;
            ldm_x4(ahi[mi][0], ahi[mi][1], ahi[mi][2], ahi[mi][3], uAhi + ad);
            ldm_x4(alo[mi][0], alo[mi][1], alo[mi][2], alo[mi][3], uAlo + ad);
        }
#pragma unroll
        for (int nb = 0; nb < 4; nb++) {     // each x4 covers n16 -> 2 frags
            uint32_t bd = bOff + nb * 16 * (PAD * 2) + kB;
            ldm_x4(bhi[nb * 2][0], bhi[nb * 2][1], bhi[nb * 2 + 1][0], bhi[nb * 2 + 1][1], uBhi + bd);
            ldm_x4(blo[nb * 2][0], blo[nb * 2][1], blo[nb * 2 + 1][0], blo[nb * 2 + 1][1], uBlo + bd);
        }
#pragma unroll
        for (int mi = 0; mi < 2; mi++)
#pragma unroll
            for (int f = 0; f < 8; f++) {
                mma_bf16(c[mi][f], ahi[mi][0], ahi[mi][1], ahi[mi][2], ahi[mi][3],
                         bhi[f][0], bhi[f][1]);
                mma_bf16(c[mi][f], alo[mi][0], alo[mi][1], alo[mi][2], alo[mi][3],
                         bhi[f][0], bhi[f][1]);
                mma_bf16(c[mi][f], ahi[mi][0], ahi[mi][1], ahi[mi][2], ahi[mi][3],
                         blo[f][0], blo[f][1]);
            }
    }

    // ---- epilogue: fragments -> C (+ bias) ----
#pragma unroll
    for (int mi = 0; mi < 2; mi++) {
        int rbase = m0 + warp_m * 32 + mi * 16 + (lane >> 2);
#pragma unroll
        for (int f = 0; f < 8; f++) {
            int col = n0 + warp_n * 64 + f * 8 + (lane & 3) * 2;
            float b0 = 0.f, b1 = 0.f;
            if (bias) { b0 = bias[col]; b1 = bias[col + 1]; }
            if (rbase < M)
                *(float2*)(C + (size_t)rbase * Ntot + col) =
                    make_float2(c[mi][f][0] + b0, c[mi][f][1] + b1);
            if (rbase + 8 < M)
                *(float2*)(C + (size_t)(rbase + 8) * Ntot + col) =
                    make_float2(c[mi][f][2] + b0, c[mi][f][3] + b1);
        }
    }
}

// ------------------------- GAT pieces ---------------------------------------
__global__ void lr_kernel(const float* __restrict__ al, const float* __restrict__ ar)
{
    int i = blockIdx.x * blockDim.x + threadIdx.x;
    if (i >= NN * 4) return;
    int h = i & 3;
    const float4* f = (const float4*)&g_feat[(size_t)(i >> 2) * HIDN + h * 32];
    const float4* a = (const float4*)&al[h * 32];
    const float4* b = (const float4*)&ar[h * 32];
    float l = 0.f, r = 0.f;
#pragma unroll
    for (int q = 0; q < 8; q++) {
        float4 fv = f[q], av = a[q], bv = b[q];
        l += fv.x * av.x + fv.y * av.y + fv.z * av.z + fv.w * av.w;
        r += fv.x * bv.x + fv.y * bv.y + fv.z * bv.z + fv.w * bv.w;
    }
    g_el[i] = l;
    g_er[i] = r;
}

__global__ void init_kernel()
{
    int i = blockIdx.x * blockDim.x + threadIdx.x;
    if (i < NN * HIDN) g_acc[i] = 0.f;
    if (i < NN * 4) {
        g_emax[i] = -INFINITY;
        g_den[i]  = 0.f;
    }
}

__global__ void edgeA_kernel(const int* __restrict__ src, const int* __restrict__ dst)
{
    int e = blockIdx.x * blockDim.x + threadIdx.x;
    if (e >= EE) return;
    int s = src[e], d = dst[e];
    float4 l = *(const float4*)&g_el[s * 4];
    float4 r = *(const float4*)&g_er[d * 4];
    float4 v;
    v.x = lrelu(l.x + r.x);
    v.y = lrelu(l.y + r.y);
    v.z = lrelu(l.z + r.z);
    v.w = lrelu(l.w + r.w);
    *(float4*)&g_e[e * 4] = v;
    atomicMaxF(&g_emax[d * 4 + 0], v.x);
    atomicMaxF(&g_emax[d * 4 + 1], v.y);
    atomicMaxF(&g_emax[d * 4 + 2], v.z);
    atomicMaxF(&g_emax[d * 4 + 3], v.w);
}

__global__ void edgeB_kernel(const int* __restrict__ src, const int* __restrict__ dst)
{
    int warp = (blockIdx.x * blockDim.x + threadIdx.x) >> 5;
    int lane = threadIdx.x & 31;
    if (warp >= EE) return;
    int s = src[warp], d = dst[warp];
    int h = lane >> 3;
    float w = __expf(g_e[warp * 4 + h] - g_emax[d * 4 + h]);
    if ((lane & 7) == 0) atomicAdd(&g_den[d * 4 + h], w);
    float4 f = *(const float4*)&g_feat[(size_t)s * HIDN + lane * 4];
    redAdd4(&g_acc[(size_t)d * HIDN + lane * 4], f.x * w, f.y * w, f.z * w, f.w * w);
}

__global__ void finalize_kernel(const float* __restrict__ bias)
{
    int i = blockIdx.x * blockDim.x + threadIdx.x;
    if (i >= NN * HIDN) return;
    int c = i & 127;
    float den = g_den[(i >> 7) * 4 + (c >> 5)];
    float v = (den > 0.f ? g_acc[i] / den : 0.f) + g_h[i] + bias[c];
    g_h[i] = v > 0.f ? v : (__expf(v) - 1.f);
}

// ------------------------- GRU ----------------------------------------------
__global__ void gru_kernel(const float* __restrict__ bhh, float* __restrict__ out)
{
    int i = blockIdx.x * blockDim.x + threadIdx.x;
    if (i >= NN * HIDN) return;
    int n = i >> 7, c = i & 127;
    const float* g = &g_gru[(size_t)n * 384];
    float r  = 1.f / (1.f + __expf(-(g[c] + bhh[c])));
    float z  = 1.f / (1.f + __expf(-(g[128 + c] + bhh[128 + c])));
    float nn = tanhf(g[256 + c] + r * bhh[256 + c]);
    out[i] = (1.f - z) * nn;
}

// ------------------------- launch -------------------------------------------
extern "C" void kernel_launch(void* const* d_in, const int* in_sizes, int n_in,
                              void* d_out, int out_size)
{
    const float* node  = (const float*)d_in[0];
    const int*   src   = (const int*)d_in[1];
    const int*   dst   = (const int*)d_in[2];
    const float* projW = (const float*)d_in[3];
    const float* projb = (const float*)d_in[4];
    const float* fcW   = (const float*)d_in[5];
    const float* attl  = (const float*)d_in[6];
    const float* attr_ = (const float*)d_in[7];
    const float* cbias = (const float*)d_in[8];
    const float* Wih   = (const float*)d_in[9];
    // d_in[10] = gru_Whh, unused (h0 == 0)
    const float* bih   = (const float*)d_in[11];
    const float* bhh   = (const float*)d_in[12];
    float* out = (float*)d_out;

    float *p_h, *p_feat, *p_gru;
    cudaGetSymbolAddress((void**)&p_h, g_h);
    cudaGetSymbolAddress((void**)&p_feat, g_feat);
    cudaGetSymbolAddress((void**)&p_gru, g_gru);

    const int SMEM_GEMM = 4 * TILE_B;  // 139264 bytes
    cudaFuncSetAttribute(gemm_tc<false>, cudaFuncAttributeMaxDynamicSharedMemorySize, SMEM_GEMM);
    cudaFuncSetAttribute(gemm_tc<true>,  cudaFuncAttributeMaxDynamicSharedMemorySize, SMEM_GEMM);

    const int MT = (NN + 127) / 128;  // 313 M-tiles

    // 1) input projection: h = node_feats @ proj_W + proj_b
    gemm_tc<false><<<dim3(MT, 1), 256, SMEM_GEMM>>>(node, projW, projb, p_h, NN, HIDN);

    // 2) 3 GAT layers
    for (int l = 0; l < 3; l++) {
        gemm_tc<false><<<dim3(MT, 1), 256, SMEM_GEMM>>>(
            p_h, fcW + (size_t)l * HIDN * HIDN, nullptr, p_feat, NN, HIDN);
        lr_kernel<<<(NN * 4 + 255) / 256, 256>>>(attl + l * HIDN, attr_ + l * HIDN);
        init_kernel<<<(NN * HIDN + 255) / 256, 256>>>();
        edgeA_kernel<<<(EE + 255) / 256, 256>>>(src, dst);
        edgeB_kernel<<<EE / 8, 256>>>(src, dst);
        finalize_kernel<<<(NN * HIDN + 255) / 256, 256>>>(cbias + l * HIDN);
    }

    // 3) 2 GRU timesteps (Whh term vanishes; h0 = 0): gi = h @ Wih^T + bih
    gemm_tc<true><<<dim3(MT, 3), 256, SMEM_GEMM>>>(p_h, Wih, bih, p_gru, NN, 384);
    gru_kernel<<<(NN * HIDN + 255) / 256, 256>>>(bhh, p_h);

    gemm_tc<true><<<dim3(MT, 3), 256, SMEM_GEMM>>>(p_h, Wih, bih, p_gru, NN, 384);
    gru_kernel<<<(NN * HIDN + 255) / 256, 256>>>(bhh, out);
}

// round 4
// speedup vs baseline: 1.4517x; 1.4517x over previous
#include <cuda_runtime.h>
#include <cuda_bf16.h>
#include <math.h>
#include <cstdint>

#define NN   40000
#define EE   640000
#define HIDN 128

// ------------------------- scratch (no allocations allowed) -----------------
__device__ __align__(16) float g_h[NN * HIDN];     // node state
__device__ __align__(16) float g_feat[NN * HIDN];  // GAT fc output
__device__ __align__(16) float g_gru[NN * 384];    // GRU gate pre-activations
__device__ __align__(16) float g_acc[NN * HIDN];   // unnormalized message sums
__device__ __align__(16) float g_el[NN * 4];
__device__ __align__(16) float g_er[NN * 4];
__device__ __align__(16) float g_emax[NN * 4];
__device__ __align__(16) float g_den[NN * 4];
// pre-split weights, [n][k] bf16, hi/lo: proj(16384) + 3*fc(16384) + Wih(49152)
#define W_ELEMS 114688
__device__ __align__(16) __nv_bfloat16 g_whi[W_ELEMS];
__device__ __align__(16) __nv_bfloat16 g_wlo[W_ELEMS];

// ------------------------- helpers ------------------------------------------
__device__ __forceinline__ uint32_t smem_u32(const void* p) {
    uint32_t a;
    asm("{ .reg .u64 t; cvta.to.shared.u64 t, %1; cvt.u32.u64 %0, t; }" : "=r"(a) : "l"(p));
    return a;
}

__device__ __forceinline__ float lrelu(float x) { return x > 0.f ? x : 0.2f * x; }

__device__ __forceinline__ void atomicMaxF(float* addr, float v) {
    if (v == 0.f) v = 0.f;  // canonicalize -0 -> +0
    if (v >= 0.f)
        atomicMax((int*)addr, __float_as_int(v));
    else
        atomicMin((unsigned int*)addr, (unsigned int)__float_as_int(v));
}

__device__ __forceinline__ void redAdd4(float* p, float a, float b, float c, float d) {
    asm volatile("red.global.add.v4.f32 [%0], {%1, %2, %3, %4};"
                 :: "l"(p), "f"(a), "f"(b), "f"(c), "f"(d) : "memory");
}

// ------------------------- mma.sync / ldmatrix primitives --------------------
__device__ __forceinline__ void ldm_x4(uint32_t& r0, uint32_t& r1, uint32_t& r2,
                                       uint32_t& r3, uint32_t addr) {
    asm volatile("ldmatrix.sync.aligned.m8n8.x4.shared.b16 {%0,%1,%2,%3}, [%4];"
                 : "=r"(r0), "=r"(r1), "=r"(r2), "=r"(r3) : "r"(addr));
}

__device__ __forceinline__ void mma_bf16(float* c, uint32_t a0, uint32_t a1,
                                         uint32_t a2, uint32_t a3,
                                         uint32_t b0, uint32_t b1) {
    asm volatile(
        "mma.sync.aligned.m16n8k16.row.col.f32.bf16.bf16.f32 "
        "{%0,%1,%2,%3}, {%4,%5,%6,%7}, {%8,%9}, {%0,%1,%2,%3};"
        : "+f"(c[0]), "+f"(c[1]), "+f"(c[2]), "+f"(c[3])
        : "r"(a0), "r"(a1), "r"(a2), "r"(a3), "r"(b0), "r"(b1));
}

// ------------------------- split-bf16 pack ----------------------------------
struct HL { uint32_t hi, lo; };
__device__ __forceinline__ HL split_pack(float a, float b) {
    __nv_bfloat16 ah = __float2bfloat16(a);
    __nv_bfloat16 bh = __float2bfloat16(b);
    __nv_bfloat16 al = __float2bfloat16(a - __bfloat162float(ah));
    __nv_bfloat16 bl = __float2bfloat16(b - __bfloat162float(bh));
    HL r;
    r.hi = ((uint32_t)__bfloat16_as_ushort(bh) << 16) | (uint32_t)__bfloat16_as_ushort(ah);
    r.lo = ((uint32_t)__bfloat16_as_ushort(bl) << 16) | (uint32_t)__bfloat16_as_ushort(al);
    return r;
}

// ------------------------- weight pre-split ----------------------------------
// out[n][k]: proj @0, fc[l] @(1+l)*16384 (both stored [k][n] in input),
// Wih @65536 (already [n][k]).
__global__ void prep_kernel(const float* __restrict__ projW,
                            const float* __restrict__ fcW,
                            const float* __restrict__ Wih)
{
    int i = blockIdx.x * blockDim.x + threadIdx.x;
    if (i >= W_ELEMS) return;
    float v;
    if (i < 65536) {
        int m = i >> 14, r = i & 16383, n = r >> 7, k = r & 127;
        v = (m == 0) ? projW[k * 128 + n] : fcW[(m - 1) * 16384 + k * 128 + n];
    } else {
        v = Wih[i - 65536];
    }
    __nv_bfloat16 hi = __float2bfloat16(v);
    g_whi[i] = hi;
    g_wlo[i] = __float2bfloat16(v - __bfloat162float(hi));
}

// ------------------------- HMMA GEMM (K = 128, tile 64x128) ------------------
// C[m, n0+j] = sum_k A[m,k] * B[n0+j, k]  (+ bias), B pre-split bf16 [n][k].
// Split-bf16: C = Ahi*Bhi + Ahi*Blo + Alo*Bhi.
// M must be a multiple of 64 (40000 = 625*64). ZACC: also zero g_acc rows.
#define RPAD 272               // padded row stride in bytes (136 bf16)
#define SM_A (64 * RPAD)       // 17408
#define SM_B (128 * RPAD)      // 34816
#define SMEM_GEMM (2 * SM_A + 2 * SM_B)  // 104448

template <bool ZACC>
__global__ __launch_bounds__(256, 2)
void gemm_hmma(const float* __restrict__ A, const __nv_bfloat16* __restrict__ Bhi,
               const __nv_bfloat16* __restrict__ Blo, const float* __restrict__ bias,
               float* __restrict__ C, int Ntot)
{
    extern __shared__ __align__(16) char smem[];
    char* sAhi = smem;
    char* sAlo = smem + SM_A;
    char* sBhi = smem + 2 * SM_A;
    char* sBlo = smem + 2 * SM_A + SM_B;

    int tid = threadIdx.x, wid = tid >> 5, lane = tid & 31;
    int m0 = blockIdx.x * 64, n0 = blockIdx.y * 128;
    int warp_m = wid >> 2, warp_n = wid & 3;   // 2 x 4 warps, 32x32 per warp

    // ---- stage A (64 rows x 128 fp32 -> split hi/lo) ----
    {
        int r = tid >> 2, q = tid & 3;       // 4 threads/row, 32 cols each
        const float4* rp = (const float4*)(A + (size_t)(m0 + r) * 128 + q * 32);
        char* dh = sAhi + r * RPAD + q * 64;
        char* dl = sAlo + r * RPAD + q * 64;
#pragma unroll
        for (int j = 0; j < 4; j++) {
            float4 v0 = rp[j * 2], v1 = rp[j * 2 + 1];
            HL p0 = split_pack(v0.x, v0.y), p1 = split_pack(v0.z, v0.w);
            HL p2 = split_pack(v1.x, v1.y), p3 = split_pack(v1.z, v1.w);
            *(uint4*)(dh + j * 16) = make_uint4(p0.hi, p1.hi, p2.hi, p3.hi);
            *(uint4*)(dl + j * 16) = make_uint4(p0.lo, p1.lo, p2.lo, p3.lo);
        }
    }
    // ---- stage B (128 rows x 128 bf16, pre-split, coalesced copy) ----
    {
        int n = tid >> 1, half = tid & 1;
        const uint4* sh = (const uint4*)(Bhi + (size_t)(n0 + n) * 128 + half * 64);
        const uint4* sl = (const uint4*)(Blo + (size_t)(n0 + n) * 128 + half * 64);
        char* dh = sBhi + n * RPAD + half * 128;
        char* dl = sBlo + n * RPAD + half * 128;
#pragma unroll
        for (int j = 0; j < 8; j++) {
            *(uint4*)(dh + j * 16) = sh[j];
            *(uint4*)(dl + j * 16) = sl[j];
        }
    }
    __syncthreads();

    // ---- mainloop ----
    float c[2][4][4];
#pragma unroll
    for (int mi = 0; mi < 2; mi++)
#pragma unroll
        for (int f = 0; f < 4; f++)
#pragma unroll
            for (int q = 0; q < 4; q++) c[mi][f][q] = 0.f;

    uint32_t uAhi = smem_u32(sAhi), uAlo = smem_u32(sAlo);
    uint32_t uBhi = smem_u32(sBhi), uBlo = smem_u32(sBlo);

    uint32_t aOff = (uint32_t)(warp_m * 32 + (lane & 15)) * RPAD + (lane >> 4) * 16;
    uint32_t bOff = (uint32_t)(warp_n * 32 + ((lane >> 4) & 1) * 8 + (lane & 7)) * RPAD
                  + ((lane >> 3) & 1) * 16;

#pragma unroll 2
    for (int k0 = 0; k0 < 128; k0 += 16) {
        uint32_t kB = (uint32_t)k0 * 2;
        uint32_t ahi[2][4], alo[2][4], bhi[4][2], blo[4][2];
#pragma unroll
        for (int mi = 0; mi < 2; mi++) {
            uint32_t ad = aOff + mi * 16 * RPAD + kB;
            ldm_x4(ahi[mi][0], ahi[mi][1], ahi[mi][2], ahi[mi][3], uAhi + ad);
            ldm_x4(alo[mi][0], alo[mi][1], alo[mi][2], alo[mi][3], uAlo + ad);
        }
#pragma unroll
        for (int nb = 0; nb < 2; nb++) {
            uint32_t bd = bOff + nb * 16 * RPAD + kB;
            ldm_x4(bhi[nb * 2][0], bhi[nb * 2][1], bhi[nb * 2 + 1][0], bhi[nb * 2 + 1][1], uBhi + bd);
            ldm_x4(blo[nb * 2][0], blo[nb * 2][1], blo[nb * 2 + 1][0], blo[nb * 2 + 1][1], uBlo + bd);
        }
#pragma unroll
        for (int mi = 0; mi < 2; mi++)
#pragma unroll
            for (int f = 0; f < 4; f++) {
                mma_bf16(c[mi][f], ahi[mi][0], ahi[mi][1], ahi[mi][2], ahi[mi][3],
                         bhi[f][0], bhi[f][1]);
                mma_bf16(c[mi][f], alo[mi][0], alo[mi][1], alo[mi][2], alo[mi][3],
                         bhi[f][0], bhi[f][1]);
                mma_bf16(c[mi][f], ahi[mi][0], ahi[mi][1], ahi[mi][2], ahi[mi][3],
                         blo[f][0], blo[f][1]);
            }
    }

    // ---- epilogue: fragments -> C (+ bias) ----
#pragma unroll
    for (int mi = 0; mi < 2; mi++) {
        int rbase = m0 + warp_m * 32 + mi * 16 + (lane >> 2);
#pragma unroll
        for (int f = 0; f < 4; f++) {
            int col = n0 + warp_n * 32 + f * 8 + (lane & 3) * 2;
            float b0 = 0.f, b1 = 0.f;
            if (bias) { b0 = bias[col]; b1 = bias[col + 1]; }
            *(float2*)(C + (size_t)rbase * Ntot + col) =
                make_float2(c[mi][f][0] + b0, c[mi][f][1] + b1);
            *(float2*)(C + (size_t)(rbase + 8) * Ntot + col) =
                make_float2(c[mi][f][2] + b0, c[mi][f][3] + b1);
        }
    }
    if (ZACC) {
        int r = tid >> 2, q = tid & 3;
        float4 z = make_float4(0.f, 0.f, 0.f, 0.f);
        float4* zp = (float4*)(g_acc + (size_t)(m0 + r) * 128 + q * 32);
#pragma unroll
        for (int j = 0; j < 8; j++) zp[j] = z;
    }
}

// ------------------------- GAT pieces ---------------------------------------
// el/er projections + reset emax/den for this layer (exactly NN*4 work items).
__global__ void lr_kernel(const float* __restrict__ al, const float* __restrict__ ar)
{
    int i = blockIdx.x * blockDim.x + threadIdx.x;
    if (i >= NN * 4) return;
    int h = i & 3;
    const float4* f = (const float4*)&g_feat[(size_t)(i >> 2) * HIDN + h * 32];
    const float4* a = (const float4*)&al[h * 32];
    const float4* b = (const float4*)&ar[h * 32];
    float l = 0.f, r = 0.f;
#pragma unroll
    for (int q = 0; q < 8; q++) {
        float4 fv = f[q], av = a[q], bv = b[q];
        l += fv.x * av.x + fv.y * av.y + fv.z * av.z + fv.w * av.w;
        r += fv.x * bv.x + fv.y * bv.y + fv.z * bv.z + fv.w * bv.w;
    }
    g_el[i] = l;
    g_er[i] = r;
    g_emax[i] = -INFINITY;
    g_den[i]  = 0.f;
}

// Pass 1: per-edge logits -> running max per (dst, head).
__global__ void edgeA_kernel(const int* __restrict__ src, const int* __restrict__ dst)
{
    int e = blockIdx.x * blockDim.x + threadIdx.x;
    if (e >= EE) return;
    int s = src[e], d = dst[e];
    float4 l = *(const float4*)&g_el[s * 4];
    float4 r = *(const float4*)&g_er[d * 4];
    atomicMaxF(&g_emax[d * 4 + 0], lrelu(l.x + r.x));
    atomicMaxF(&g_emax[d * 4 + 1], lrelu(l.y + r.y));
    atomicMaxF(&g_emax[d * 4 + 2], lrelu(l.z + r.z));
    atomicMaxF(&g_emax[d * 4 + 3], lrelu(l.w + r.w));
}

// Pass 2: recompute logit, w = exp(e - max); denom += w; acc[dst] += w*feat[src].
__global__ void edgeB_kernel(const int* __restrict__ src, const int* __restrict__ dst)
{
    int warp = (blockIdx.x * blockDim.x + threadIdx.x) >> 5;
    int lane = threadIdx.x & 31;
    if (warp >= EE) return;
    int s = src[warp], d = dst[warp];
    int h = lane >> 3;
    float e = lrelu(g_el[s * 4 + h] + g_er[d * 4 + h]);
    float w = __expf(e - g_emax[d * 4 + h]);
    if ((lane & 7) == 0) atomicAdd(&g_den[d * 4 + h], w);
    float4 f = *(const float4*)&g_feat[(size_t)s * HIDN + lane * 4];
    redAdd4(&g_acc[(size_t)d * HIDN + lane * 4], f.x * w, f.y * w, f.z * w, f.w * w);
}

// Epilogue: h = elu(acc/denom + h + bias)
__global__ void finalize_kernel(const float* __restrict__ bias)
{
    int i = blockIdx.x * blockDim.x + threadIdx.x;
    if (i >= NN * HIDN) return;
    int c = i & 127;
    float den = g_den[(i >> 7) * 4 + (c >> 5)];
    float v = (den > 0.f ? g_acc[i] / den : 0.f) + g_h[i] + bias[c];
    g_h[i] = v > 0.f ? v : (__expf(v) - 1.f);
}

// ------------------------- GRU ----------------------------------------------
__global__ void gru_kernel(const float* __restrict__ bhh, float* __restrict__ out)
{
    int i = blockIdx.x * blockDim.x + threadIdx.x;
    if (i >= NN * HIDN) return;
    int n = i >> 7, c = i & 127;
    const float* g = &g_gru[(size_t)n * 384];
    float r  = 1.f / (1.f + __expf(-(g[c] + bhh[c])));
    float z  = 1.f / (1.f + __expf(-(g[128 + c] + bhh[128 + c])));
    float nn = tanhf(g[256 + c] + r * bhh[256 + c]);
    out[i] = (1.f - z) * nn;
}

// ------------------------- launch -------------------------------------------
extern "C" void kernel_launch(void* const* d_in, const int* in_sizes, int n_in,
                              void* d_out, int out_size)
{
    const float* node  = (const float*)d_in[0];
    const int*   src   = (const int*)d_in[1];
    const int*   dst   = (const int*)d_in[2];
    const float* projW = (const float*)d_in[3];
    const float* projb = (const float*)d_in[4];
    const float* fcW   = (const float*)d_in[5];
    const float* attl  = (const float*)d_in[6];
    const float* attr_ = (const float*)d_in[7];
    const float* cbias = (const float*)d_in[8];
    const float* Wih   = (const float*)d_in[9];
    // d_in[10] = gru_Whh, unused (h0 == 0)
    const float* bih   = (const float*)d_in[11];
    const float* bhh   = (const float*)d_in[12];
    float* out = (float*)d_out;

    float *p_h, *p_feat, *p_gru;
    __nv_bfloat16 *p_whi, *p_wlo;
    cudaGetSymbolAddress((void**)&p_h, g_h);
    cudaGetSymbolAddress((void**)&p_feat, g_feat);
    cudaGetSymbolAddress((void**)&p_gru, g_gru);
    cudaGetSymbolAddress((void**)&p_whi, g_whi);
    cudaGetSymbolAddress((void**)&p_wlo, g_wlo);

    cudaFuncSetAttribute(gemm_hmma<false>, cudaFuncAttributeMaxDynamicSharedMemorySize, SMEM_GEMM);
    cudaFuncSetAttribute(gemm_hmma<true>,  cudaFuncAttributeMaxDynamicSharedMemorySize, SMEM_GEMM);

    const int MT = NN / 64;  // 625, exact

    // 0) split weights to bf16 hi/lo
    prep_kernel<<<(W_ELEMS + 255) / 256, 256>>>(projW, fcW, Wih);

    // 1) input projection: h = node_feats @ proj_W + proj_b
    gemm_hmma<false><<<dim3(MT, 1), 256, SMEM_GEMM>>>(node, p_whi, p_wlo, projb, p_h, HIDN);

    // 2) 3 GAT layers  (fc gemm also zeroes g_acc; lr resets emax/den)
    for (int l = 0; l < 3; l++) {
        size_t off = (size_t)(1 + l) * 16384;
        gemm_hmma<true><<<dim3(MT, 1), 256, SMEM_GEMM>>>(
            p_h, p_whi + off, p_wlo + off, nullptr, p_feat, HIDN);
        lr_kernel<<<(NN * 4 + 255) / 256, 256>>>(attl + l * HIDN, attr_ + l * HIDN);
        edgeA_kernel<<<(EE + 255) / 256, 256>>>(src, dst);
        edgeB_kernel<<<EE / 8, 256>>>(src, dst);
        finalize_kernel<<<(NN * HIDN + 255) / 256, 256>>>(cbias + l * HIDN);
    }

    // 3) 2 GRU timesteps (Whh vanishes; h0 = 0): gi = h @ Wih^T + bih
    gemm_hmma<false><<<dim3(MT, 3), 256, SMEM_GEMM>>>(p_h, p_whi + 65536, p_wlo + 65536, bih, p_gru, 384);
    gru_kernel<<<(NN * HIDN + 255) / 256, 256>>>(bhh, p_h);

    gemm_hmma<false><<<dim3(MT, 3), 256, SMEM_GEMM>>>(p_h, p_whi + 65536, p_wlo + 65536, bih, p_gru, 384);
    gru_kernel<<<(NN * HIDN + 255) / 256, 256>>>(bhh, out);
}

// round 5
// speedup vs baseline: 2.1154x; 1.4572x over previous
#include <cuda_runtime.h>
#include <cuda_bf16.h>
#include <math.h>
#include <cstdint>

#define NN   40000
#define EE   640000
#define HIDN 128

// ------------------------- scratch (no allocations allowed) -----------------
__device__ __align__(16) float g_h[NN * HIDN];     // node state
__device__ __align__(16) float g_feat[NN * HIDN];  // GAT fc output
__device__ __align__(16) float g_gru[NN * 384];    // GRU gate pre-activations
__device__ __align__(16) float g_el[NN * 4];
__device__ __align__(16) float g_er[NN * 4];
// CSR by dst (built once per call, reused for 3 layers)
__device__ int g_deg[NN];
__device__ int g_off[NN + 1];
__device__ int g_pos[NN];
__device__ int g_csrc[EE];
// pre-split weights, [n][k] bf16, hi/lo: proj(16384) + 3*fc(16384) + Wih(49152)
#define W_ELEMS 114688
__device__ __align__(16) __nv_bfloat16 g_whi[W_ELEMS];
__device__ __align__(16) __nv_bfloat16 g_wlo[W_ELEMS];

// ------------------------- helpers ------------------------------------------
__device__ __forceinline__ uint32_t smem_u32(const void* p) {
    uint32_t a;
    asm("{ .reg .u64 t; cvta.to.shared.u64 t, %1; cvt.u32.u64 %0, t; }" : "=r"(a) : "l"(p));
    return a;
}

__device__ __forceinline__ float lrelu(float x) { return x > 0.f ? x : 0.2f * x; }

// ------------------------- mma.sync / ldmatrix primitives --------------------
__device__ __forceinline__ void ldm_x4(uint32_t& r0, uint32_t& r1, uint32_t& r2,
                                       uint32_t& r3, uint32_t addr) {
    asm volatile("ldmatrix.sync.aligned.m8n8.x4.shared.b16 {%0,%1,%2,%3}, [%4];"
                 : "=r"(r0), "=r"(r1), "=r"(r2), "=r"(r3) : "r"(addr));
}

__device__ __forceinline__ void mma_bf16(float* c, uint32_t a0, uint32_t a1,
                                         uint32_t a2, uint32_t a3,
                                         uint32_t b0, uint32_t b1) {
    asm volatile(
        "mma.sync.aligned.m16n8k16.row.col.f32.bf16.bf16.f32 "
        "{%0,%1,%2,%3}, {%4,%5,%6,%7}, {%8,%9}, {%0,%1,%2,%3};"
        : "+f"(c[0]), "+f"(c[1]), "+f"(c[2]), "+f"(c[3])
        : "r"(a0), "r"(a1), "r"(a2), "r"(a3), "r"(b0), "r"(b1));
}

// ------------------------- split-bf16 pack ----------------------------------
struct HL { uint32_t hi, lo; };
__device__ __forceinline__ HL split_pack(float a, float b) {
    __nv_bfloat16 ah = __float2bfloat16(a);
    __nv_bfloat16 bh = __float2bfloat16(b);
    __nv_bfloat16 al = __float2bfloat16(a - __bfloat162float(ah));
    __nv_bfloat16 bl = __float2bfloat16(b - __bfloat162float(bh));
    HL r;
    r.hi = ((uint32_t)__bfloat16_as_ushort(bh) << 16) | (uint32_t)__bfloat16_as_ushort(ah);
    r.lo = ((uint32_t)__bfloat16_as_ushort(bl) << 16) | (uint32_t)__bfloat16_as_ushort(al);
    return r;
}

// ------------------------- weight pre-split + deg reset ----------------------
__global__ void prep_kernel(const float* __restrict__ projW,
                            const float* __restrict__ fcW,
                            const float* __restrict__ Wih)
{
    int i = blockIdx.x * blockDim.x + threadIdx.x;
    if (i >= W_ELEMS) return;
    if (i < NN) g_deg[i] = 0;
    float v;
    if (i < 65536) {
        int m = i >> 14, r = i & 16383, n = r >> 7, k = r & 127;
        v = (m == 0) ? projW[k * 128 + n] : fcW[(m - 1) * 16384 + k * 128 + n];
    } else {
        v = Wih[i - 65536];
    }
    __nv_bfloat16 hi = __float2bfloat16(v);
    g_whi[i] = hi;
    g_wlo[i] = __float2bfloat16(v - __bfloat162float(hi));
}

// ------------------------- CSR build ----------------------------------------
__global__ void count_kernel(const int* __restrict__ dst)
{
    int e = blockIdx.x * blockDim.x + threadIdx.x;
    if (e < EE) atomicAdd(&g_deg[dst[e]], 1);
}

#define SCAN_CHUNK 40
__global__ __launch_bounds__(1024) void scan_kernel()
{
    __shared__ int ssum[1024];
    int t = threadIdx.x;
    int base = t * SCAN_CHUNK;
    int s = 0;
#pragma unroll
    for (int i = 0; i < SCAN_CHUNK; i++)
        if (base + i < NN) s += g_deg[base + i];
    ssum[t] = s;
    __syncthreads();
    for (int off = 1; off < 1024; off <<= 1) {
        int v = (t >= off) ? ssum[t - off] : 0;
        __syncthreads();
        ssum[t] += v;
        __syncthreads();
    }
    int run = (t == 0) ? 0 : ssum[t - 1];
#pragma unroll
    for (int i = 0; i < SCAN_CHUNK; i++)
        if (base + i < NN) {
            g_off[base + i] = run;
            g_pos[base + i] = run;
            run += g_deg[base + i];
        }
    if (t == 0) g_off[NN] = EE;
}

__global__ void scatter_kernel(const int* __restrict__ src, const int* __restrict__ dst)
{
    int e = blockIdx.x * blockDim.x + threadIdx.x;
    if (e >= EE) return;
    int p = atomicAdd(&g_pos[dst[e]], 1);
    g_csrc[p] = src[e];
}

// ------------------------- HMMA GEMM (K = 128, tile 64x128) ------------------
// C[m, n0+j] = sum_k A[m,k] * B[n0+j, k]  (+ bias), B pre-split bf16 [n][k].
// Split-bf16: C = Ahi*Bhi + Ahi*Blo + Alo*Bhi.  M multiple of 64.
// LRF: fused attention projections (requires Ntot==128, grid.y==1):
//   warp_n == head; el[m,h] = sum_j C[m, h*32+j]*attl[h*32+j], er likewise.
#define RPAD 272               // padded row stride in bytes (136 bf16)
#define SM_A (64 * RPAD)       // 17408
#define SM_B (128 * RPAD)      // 34816
#define SMEM_GEMM (2 * SM_A + 2 * SM_B)  // 104448

template <bool LRF>
__global__ __launch_bounds__(256, 2)
void gemm_hmma(const float* __restrict__ A, const __nv_bfloat16* __restrict__ Bhi,
               const __nv_bfloat16* __restrict__ Blo, const float* __restrict__ bias,
               float* __restrict__ C, int Ntot,
               const float* __restrict__ attl, const float* __restrict__ attr)
{
    extern __shared__ __align__(16) char smem[];
    char* sAhi = smem;
    char* sAlo = smem + SM_A;
    char* sBhi = smem + 2 * SM_A;
    char* sBlo = smem + 2 * SM_A + SM_B;

    int tid = threadIdx.x, wid = tid >> 5, lane = tid & 31;
    int m0 = blockIdx.x * 64, n0 = blockIdx.y * 128;
    int warp_m = wid >> 2, warp_n = wid & 3;   // 2 x 4 warps, 32x32 per warp

    // ---- stage A (64 rows x 128 fp32 -> split hi/lo) ----
    {
        int r = tid >> 2, q = tid & 3;       // 4 threads/row, 32 cols each
        const float4* rp = (const float4*)(A + (size_t)(m0 + r) * 128 + q * 32);
        char* dh = sAhi + r * RPAD + q * 64;
        char* dl = sAlo + r * RPAD + q * 64;
#pragma unroll
        for (int j = 0; j < 4; j++) {
            float4 v0 = rp[j * 2], v1 = rp[j * 2 + 1];
            HL p0 = split_pack(v0.x, v0.y), p1 = split_pack(v0.z, v0.w);
            HL p2 = split_pack(v1.x, v1.y), p3 = split_pack(v1.z, v1.w);
            *(uint4*)(dh + j * 16) = make_uint4(p0.hi, p1.hi, p2.hi, p3.hi);
            *(uint4*)(dl + j * 16) = make_uint4(p0.lo, p1.lo, p2.lo, p3.lo);
        }
    }
    // ---- stage B (128 rows x 128 bf16, pre-split, coalesced copy) ----
    {
        int n = tid >> 1, half = tid & 1;
        const uint4* sh = (const uint4*)(Bhi + (size_t)(n0 + n) * 128 + half * 64);
        const uint4* sl = (const uint4*)(Blo + (size_t)(n0 + n) * 128 + half * 64);
        char* dh = sBhi + n * RPAD + half * 128;
        char* dl = sBlo + n * RPAD + half * 128;
#pragma unroll
        for (int j = 0; j < 8; j++) {
            *(uint4*)(dh + j * 16) = sh[j];
            *(uint4*)(dl + j * 16) = sl[j];
        }
    }
    __syncthreads();

    // ---- mainloop ----
    float c[2][4][4];
#pragma unroll
    for (int mi = 0; mi < 2; mi++)
#pragma unroll
        for (int f = 0; f < 4; f++)
#pragma unroll
            for (int q = 0; q < 4; q++) c[mi][f][q] = 0.f;

    uint32_t uAhi = smem_u32(sAhi), uAlo = smem_u32(sAlo);
    uint32_t uBhi = smem_u32(sBhi), uBlo = smem_u32(sBlo);

    uint32_t aOff = (uint32_t)(warp_m * 32 + (lane & 15)) * RPAD + (lane >> 4) * 16;
    uint32_t bOff = (uint32_t)(warp_n * 32 + ((lane >> 4) & 1) * 8 + (lane & 7)) * RPAD
                  + ((lane >> 3) & 1) * 16;

#pragma unroll 2
    for (int k0 = 0; k0 < 128; k0 += 16) {
        uint32_t kB = (uint32_t)k0 * 2;
        uint32_t ahi[2][4], alo[2][4], bhi[4][2], blo[4][2];
#pragma unroll
        for (int mi = 0; mi < 2; mi++) {
            uint32_t ad = aOff + mi * 16 * RPAD + kB;
            ldm_x4(ahi[mi][0], ahi[mi][1], ahi[mi][2], ahi[mi][3], uAhi + ad);
            ldm_x4(alo[mi][0], alo[mi][1], alo[mi][2], alo[mi][3], uAlo + ad);
        }
#pragma unroll
        for (int nb = 0; nb < 2; nb++) {
            uint32_t bd = bOff + nb * 16 * RPAD + kB;
            ldm_x4(bhi[nb * 2][0], bhi[nb * 2][1], bhi[nb * 2 + 1][0], bhi[nb * 2 + 1][1], uBhi + bd);
            ldm_x4(blo[nb * 2][0], blo[nb * 2][1], blo[nb * 2 + 1][0], blo[nb * 2 + 1][1], uBlo + bd);
        }
#pragma unroll
        for (int mi = 0; mi < 2; mi++)
#pragma unroll
            for (int f = 0; f < 4; f++) {
                mma_bf16(c[mi][f], ahi[mi][0], ahi[mi][1], ahi[mi][2], ahi[mi][3],
                         bhi[f][0], bhi[f][1]);
                mma_bf16(c[mi][f], alo[mi][0], alo[mi][1], alo[mi][2], alo[mi][3],
                         bhi[f][0], bhi[f][1]);
                mma_bf16(c[mi][f], ahi[mi][0], ahi[mi][1], ahi[mi][2], ahi[mi][3],
                         blo[f][0], blo[f][1]);
            }
    }

    // ---- epilogue: fragments -> C (+ bias) ----
#pragma unroll
    for (int mi = 0; mi < 2; mi++) {
        int rbase = m0 + warp_m * 32 + mi * 16 + (lane >> 2);
#pragma unroll
        for (int f = 0; f < 4; f++) {
            int col = n0 + warp_n * 32 + f * 8 + (lane & 3) * 2;
            float b0 = 0.f, b1 = 0.f;
            if (bias) { b0 = bias[col]; b1 = bias[col + 1]; }
            *(float2*)(C + (size_t)rbase * Ntot + col) =
                make_float2(c[mi][f][0] + b0, c[mi][f][1] + b1);
            *(float2*)(C + (size_t)(rbase + 8) * Ntot + col) =
                make_float2(c[mi][f][2] + b0, c[mi][f][3] + b1);
        }
    }
    // ---- fused el/er: warp_n == head, warp's 32 cols == that head's dims ----
    if (LRF) {
#pragma unroll
        for (int mi = 0; mi < 2; mi++) {
            float el0 = 0.f, el1 = 0.f, er0 = 0.f, er1 = 0.f;
#pragma unroll
            for (int f = 0; f < 4; f++) {
                int jj = warp_n * 32 + f * 8 + (lane & 3) * 2;
                float a0 = attl[jj], a1 = attl[jj + 1];
                float b0 = attr[jj], b1 = attr[jj + 1];
                el0 += c[mi][f][0] * a0 + c[mi][f][1] * a1;
                el1 += c[mi][f][2] * a0 + c[mi][f][3] * a1;
                er0 += c[mi][f][0] * b0 + c[mi][f][1] * b1;
                er1 += c[mi][f][2] * b0 + c[mi][f][3] * b1;
            }
#pragma unroll
            for (int m = 1; m < 4; m <<= 1) {
                el0 += __shfl_xor_sync(0xffffffffu, el0, m);
                el1 += __shfl_xor_sync(0xffffffffu, el1, m);
                er0 += __shfl_xor_sync(0xffffffffu, er0, m);
                er1 += __shfl_xor_sync(0xffffffffu, er1, m);
            }
            if ((lane & 3) == 0) {
                int r0 = m0 + warp_m * 32 + mi * 16 + (lane >> 2);
                g_el[r0 * 4 + warp_n] = el0;
                g_er[r0 * 4 + warp_n] = er0;
                g_el[(r0 + 8) * 4 + warp_n] = el1;
                g_er[(r0 + 8) * 4 + warp_n] = er1;
            }
        }
    }
}

// ------------------------- fused GAT gather (softmax + aggregate + ELU) ------
// One warp per dst node. No max-subtraction (logits are O(1); exp(e)/sum exp(e)
// is the identical softmax). acc/den in registers; epilogue fused.
__global__ __launch_bounds__(256) void gat_gather(const float* __restrict__ bias)
{
    int w = (blockIdx.x * blockDim.x + threadIdx.x) >> 5;
    int lane = threadIdx.x & 31;
    if (w >= NN) return;
    int h = lane >> 3;
    float er_v = g_er[w * 4 + h];
    int beg = g_off[w], end = g_off[w + 1];
    float den = 0.f;
    float4 acc = make_float4(0.f, 0.f, 0.f, 0.f);
#pragma unroll 2
    for (int i = beg; i < end; i++) {
        int s = g_csrc[i];
        float e = lrelu(g_el[s * 4 + h] + er_v);
        float wt = __expf(e);
        den += wt;
        float4 f = *(const float4*)&g_feat[(size_t)s * HIDN + lane * 4];
        acc.x += wt * f.x;
        acc.y += wt * f.y;
        acc.z += wt * f.z;
        acc.w += wt * f.w;
    }
    float inv = den > 0.f ? 1.f / den : 0.f;
    float4 hv = *(const float4*)&g_h[(size_t)w * HIDN + lane * 4];
    const float4 bv = *(const float4*)&bias[lane * 4];
    float4 v;
    v.x = acc.x * inv + hv.x + bv.x;
    v.y = acc.y * inv + hv.y + bv.y;
    v.z = acc.z * inv + hv.z + bv.z;
    v.w = acc.w * inv + hv.w + bv.w;
    v.x = v.x > 0.f ? v.x : (__expf(v.x) - 1.f);
    v.y = v.y > 0.f ? v.y : (__expf(v.y) - 1.f);
    v.z = v.z > 0.f ? v.z : (__expf(v.z) - 1.f);
    v.w = v.w > 0.f ? v.w : (__expf(v.w) - 1.f);
    *(float4*)&g_h[(size_t)w * HIDN + lane * 4] = v;
}

// ------------------------- GRU ----------------------------------------------
__global__ void gru_kernel(const float* __restrict__ bhh, float* __restrict__ out)
{
    int i = blockIdx.x * blockDim.x + threadIdx.x;
    if (i >= NN * HIDN) return;
    int n = i >> 7, c = i & 127;
    const float* g = &g_gru[(size_t)n * 384];
    float r  = 1.f / (1.f + __expf(-(g[c] + bhh[c])));
    float z  = 1.f / (1.f + __expf(-(g[128 + c] + bhh[128 + c])));
    float nn = tanhf(g[256 + c] + r * bhh[256 + c]);
    out[i] = (1.f - z) * nn;
}

// ------------------------- launch -------------------------------------------
extern "C" void kernel_launch(void* const* d_in, const int* in_sizes, int n_in,
                              void* d_out, int out_size)
{
    const float* node  = (const float*)d_in[0];
    const int*   src   = (const int*)d_in[1];
    const int*   dst   = (const int*)d_in[2];
    const float* projW = (const float*)d_in[3];
    const float* projb = (const float*)d_in[4];
    const float* fcW   = (const float*)d_in[5];
    const float* attl  = (const float*)d_in[6];
    const float* attr_ = (const float*)d_in[7];
    const float* cbias = (const float*)d_in[8];
    const float* Wih   = (const float*)d_in[9];
    // d_in[10] = gru_Whh, unused (h0 == 0)
    const float* bih   = (const float*)d_in[11];
    const float* bhh   = (const float*)d_in[12];
    float* out = (float*)d_out;

    float *p_h, *p_feat, *p_gru;
    __nv_bfloat16 *p_whi, *p_wlo;
    cudaGetSymbolAddress((void**)&p_h, g_h);
    cudaGetSymbolAddress((void**)&p_feat, g_feat);
    cudaGetSymbolAddress((void**)&p_gru, g_gru);
    cudaGetSymbolAddress((void**)&p_whi, g_whi);
    cudaGetSymbolAddress((void**)&p_wlo, g_wlo);

    cudaFuncSetAttribute(gemm_hmma<false>, cudaFuncAttributeMaxDynamicSharedMemorySize, SMEM_GEMM);
    cudaFuncSetAttribute(gemm_hmma<true>,  cudaFuncAttributeMaxDynamicSharedMemorySize, SMEM_GEMM);

    const int MT = NN / 64;  // 625, exact

    // 0) split weights, zero degrees, build CSR by dst (reused for all layers)
    prep_kernel<<<(W_ELEMS + 255) / 256, 256>>>(projW, fcW, Wih);
    count_kernel<<<(EE + 255) / 256, 256>>>(dst);
    scan_kernel<<<1, 1024>>>();
    scatter_kernel<<<(EE + 255) / 256, 256>>>(src, dst);

    // 1) input projection: h = node_feats @ proj_W + proj_b
    gemm_hmma<false><<<dim3(MT, 1), 256, SMEM_GEMM>>>(node, p_whi, p_wlo, projb,
                                                      p_h, HIDN, nullptr, nullptr);

    // 2) 3 GAT layers: fc gemm (+fused el/er), then fused gather+softmax+ELU
    for (int l = 0; l < 3; l++) {
        size_t off = (size_t)(1 + l) * 16384;
        gemm_hmma<true><<<dim3(MT, 1), 256, SMEM_GEMM>>>(
            p_h, p_whi + off, p_wlo + off, nullptr, p_feat, HIDN,
            attl + l * HIDN, attr_ + l * HIDN);
        gat_gather<<<NN * 32 / 256, 256>>>(cbias + l * HIDN);
    }

    // 3) 2 GRU timesteps (Whh vanishes; h0 = 0): gi = h @ Wih^T + bih
    gemm_hmma<false><<<dim3(MT, 3), 256, SMEM_GEMM>>>(p_h, p_whi + 65536, p_wlo + 65536,
                                                      bih, p_gru, 384, nullptr, nullptr);
    gru_kernel<<<(NN * HIDN + 255) / 256, 256>>>(bhh, p_h);

    gemm_hmma<false><<<dim3(MT, 3), 256, SMEM_GEMM>>>(p_h, p_whi + 65536, p_wlo + 65536,
                                                      bih, p_gru, 384, nullptr, nullptr);
    gru_kernel<<<(NN * HIDN + 255) / 256, 256>>>(bhh, out);
}